// round 2
// baseline (speedup 1.0000x reference)
#include <cuda_runtime.h>
#include <cuda_bf16.h>

// PathBasedLoss: mean over B rows of (group[argmax(pred[b,:8])] != group[target[b]])
// groups: classes 0-2 -> 0, 3-5 -> 1, 6-7 -> 2
// predictions: float32 [B, 8], targets: int32 [B] (JAX downcasts int64 w/o x64),
// output: float32 scalar.

static __device__ unsigned int g_mismatch_count;

__global__ void pbl_init_kernel() {
    g_mismatch_count = 0u;
}

__device__ __forceinline__ int class_to_group(int c) {
    return (c < 3) ? 0 : ((c < 6) ? 1 : 2);
}

__global__ void __launch_bounds__(256) pbl_main_kernel(
    const float4* __restrict__ preds,   // 2 float4 per row
    const int* __restrict__ targets,    // int32 targets
    int batch)
{
    int tid = blockIdx.x * blockDim.x + threadIdx.x;
    int stride = gridDim.x * blockDim.x;

    unsigned int local = 0;
    for (int r = tid; r < batch; r += stride) {
        float4 a = preds[2 * r];
        float4 b = preds[2 * r + 1];
        int t = targets[r];

        float v0 = a.x, v1 = a.y, v2 = a.z, v3 = a.w;
        float v4 = b.x, v5 = b.y, v6 = b.z, v7 = b.w;

        // first-max argmax (strict >), matching jnp.argmax tie-break
        int best = 0; float bv = v0;
        if (v1 > bv) { bv = v1; best = 1; }
        if (v2 > bv) { bv = v2; best = 2; }
        if (v3 > bv) { bv = v3; best = 3; }
        if (v4 > bv) { bv = v4; best = 4; }
        if (v5 > bv) { bv = v5; best = 5; }
        if (v6 > bv) { bv = v6; best = 6; }
        if (v7 > bv) { bv = v7; best = 7; }

        int pg = class_to_group(best);
        int tg = class_to_group(t);
        local += (unsigned int)(pg != tg);
    }

    // warp reduce
    #pragma unroll
    for (int off = 16; off > 0; off >>= 1)
        local += __shfl_down_sync(0xffffffffu, local, off);

    if ((threadIdx.x & 31) == 0 && local)
        atomicAdd(&g_mismatch_count, local);
}

__global__ void pbl_finalize_kernel(float* __restrict__ out, float inv_batch) {
    out[0] = (float)g_mismatch_count * inv_batch;
}

extern "C" void kernel_launch(void* const* d_in, const int* in_sizes, int n_in,
                              void* d_out, int out_size) {
    const float4* preds = (const float4*)d_in[0];
    const int* targets = (const int*)d_in[1];
    float* out = (float*)d_out;

    int batch = in_sizes[1];  // targets element count = B

    pbl_init_kernel<<<1, 1>>>();

    const int threads = 256;
    const int rows_per_thread = 8;
    int blocks = (batch + threads * rows_per_thread - 1) / (threads * rows_per_thread);
    pbl_main_kernel<<<blocks, threads>>>(preds, targets, batch);

    pbl_finalize_kernel<<<1, 1>>>(out, 1.0f / (float)batch);
}

// round 3
// speedup vs baseline: 1.2314x; 1.2314x over previous
#include <cuda_runtime.h>
#include <cuda_bf16.h>

// PathBasedLoss: mean over B rows of (group[argmax(pred[b,:8])] != group[target[b]])
// groups: classes 0-2 -> 0, 3-5 -> 1, 6-7 -> 2
// predictions: float32 [B, 8], targets: int32 [B], output: float32 scalar.
//
// Single-kernel design: per-block partial counts + self-resetting ticket
// (atomicInc wraps to 0 after gridDim arrivals -> graph-replay safe, no init).

#define PBL_THREADS 256
#define PBL_ROWS_PER_THREAD 8
#define PBL_CHUNK (PBL_THREADS * PBL_ROWS_PER_THREAD)  // rows per block
#define PBL_MAX_BLOCKS 8192

static __device__ unsigned int g_partials[PBL_MAX_BLOCKS];
static __device__ unsigned int g_ticket;  // zero-init; self-wraps each launch

__device__ __forceinline__ int class_to_group(int c) {
    return (c < 3) ? 0 : ((c < 6) ? 1 : 2);
}

__global__ void __launch_bounds__(PBL_THREADS) pbl_fused_kernel(
    const float4* __restrict__ preds,   // 2 float4 per row
    const int* __restrict__ targets,    // int32 targets
    float* __restrict__ out,
    int batch, float inv_batch)
{
    const int base = blockIdx.x * PBL_CHUNK + threadIdx.x;

    unsigned int local = 0;
    #pragma unroll
    for (int i = 0; i < PBL_ROWS_PER_THREAD; i++) {
        int r = base + i * PBL_THREADS;
        if (r < batch) {
            float4 a = preds[2 * r];
            float4 b = preds[2 * r + 1];
            int t = targets[r];

            // first-max argmax (strict >), matching jnp.argmax tie-break
            int best = 0; float bv = a.x;
            if (a.y > bv) { bv = a.y; best = 1; }
            if (a.z > bv) { bv = a.z; best = 2; }
            if (a.w > bv) { bv = a.w; best = 3; }
            if (b.x > bv) { bv = b.x; best = 4; }
            if (b.y > bv) { bv = b.y; best = 5; }
            if (b.z > bv) { bv = b.z; best = 6; }
            if (b.w > bv) { bv = b.w; best = 7; }

            local += (unsigned int)(class_to_group(best) != class_to_group(t));
        }
    }

    // intra-warp reduce
    #pragma unroll
    for (int off = 16; off > 0; off >>= 1)
        local += __shfl_down_sync(0xffffffffu, local, off);

    // intra-block reduce via shared
    __shared__ unsigned int warp_sums[PBL_THREADS / 32];
    __shared__ bool is_last;
    int lane = threadIdx.x & 31;
    int wid = threadIdx.x >> 5;
    if (lane == 0) warp_sums[wid] = local;
    __syncthreads();

    if (threadIdx.x == 0) {
        unsigned int blk = 0;
        #pragma unroll
        for (int w = 0; w < PBL_THREADS / 32; w++) blk += warp_sums[w];
        g_partials[blockIdx.x] = blk;
        __threadfence();
        // self-wrapping ticket: returns to 0 after gridDim arrivals
        unsigned int old = atomicInc(&g_ticket, gridDim.x - 1);
        is_last = (old == gridDim.x - 1);
    }
    __syncthreads();

    if (is_last) {
        // last block: sum all partials and write the mean
        unsigned int sum = 0;
        for (int i = threadIdx.x; i < gridDim.x; i += PBL_THREADS)
            sum += g_partials[i];
        #pragma unroll
        for (int off = 16; off > 0; off >>= 1)
            sum += __shfl_down_sync(0xffffffffu, sum, off);
        if (lane == 0) warp_sums[wid] = sum;
        __syncthreads();
        if (threadIdx.x == 0) {
            unsigned int total = 0;
            #pragma unroll
            for (int w = 0; w < PBL_THREADS / 32; w++) total += warp_sums[w];
            out[0] = (float)total * inv_batch;
        }
    }
}

extern "C" void kernel_launch(void* const* d_in, const int* in_sizes, int n_in,
                              void* d_out, int out_size) {
    const float4* preds = (const float4*)d_in[0];
    const int* targets = (const int*)d_in[1];
    float* out = (float*)d_out;

    int batch = in_sizes[1];  // targets element count = B
    int blocks = (batch + PBL_CHUNK - 1) / PBL_CHUNK;
    if (blocks > PBL_MAX_BLOCKS) blocks = PBL_MAX_BLOCKS;  // safety (B=4M -> 2048)

    pbl_fused_kernel<<<blocks, PBL_THREADS>>>(preds, targets, out, batch,
                                              1.0f / (float)batch);
}